// round 6
// baseline (speedup 1.0000x reference)
#include <cuda_runtime.h>

// Conditional encoding: 2-layer LSTM (B=1024, T=256, D=50, H=64) + MLP head.
// x@Wih^T+bias precomputed per vocab entry (32.8MB/layer L2 table).
// Recurrence: 256 CTAs x 4 rows, 2 CTAs/SM, 512 thr: thread = (gate row,
// k-half). Each thread does half a gate dot (16 ffma2/row); halves merge via
// pre2[] smem; combine by kh=0 threads; 8 warps/SMSP for latency hiding.

#define BB   1024
#define TT   256
#define DD   50
#define HH   64
#define GG   256   // 4*H
#define VV   32004
#define BT   4     // batch rows per recurrent CTA
#define NCTA 256
#define NTHR 512
#define HP   72    // padded h row stride
#define VB   1001  // ceil(32004/32)

typedef unsigned long long u64;

__device__ float g_tab0[(long)VV * GG];   // layer-1 gate-x table (32.8 MB)
__device__ float g_tab1[(long)VV * GG];   // layer-2 gate-x table

__device__ __forceinline__ u64 pk2(float a, float b) {
    u64 r; asm("mov.b64 %0, {%1, %2};" : "=l"(r) : "f"(a), "f"(b)); return r;
}
__device__ __forceinline__ u64 ffma2(u64 a, u64 b, u64 c) {
    u64 d; asm("fma.rn.f32x2 %0, %1, %2, %3;" : "=l"(d) : "l"(a), "l"(b), "l"(c)); return d;
}
__device__ __forceinline__ float pairsum(u64 a) {
    float x, y; asm("mov.b64 {%0, %1}, %2;" : "=f"(x), "=f"(y) : "l"(a)); return x + y;
}
__device__ __forceinline__ float tanha(float x) {
    float y; asm("tanh.approx.f32 %0, %1;" : "=f"(y) : "f"(x)); return y;
}
__device__ __forceinline__ float siga(float x) {
    return fmaf(0.5f, tanha(0.5f * x), 0.5f);
}

// ---------------- precompute GEMM: tab[v][g] = emb[v].Wih[g] + bih[g]+bhh[g] ----
__global__ void __launch_bounds__(256) precompute_kernel(
    const float* __restrict__ emb,
    const float* __restrict__ WihA, const float* __restrict__ biA, const float* __restrict__ bhA,
    const float* __restrict__ WihB, const float* __restrict__ biB, const float* __restrict__ bhB)
{
    const int layer = blockIdx.x >= VB;
    const int vb    = layer ? blockIdx.x - VB : blockIdx.x;
    const float* Wih = layer ? WihB : WihA;
    const float* bi  = layer ? biB  : biA;
    const float* bh  = layer ? bhB  : bhA;
    float* tab = layer ? g_tab1 : g_tab0;

    __shared__ float xs[32][DD];
    __shared__ __align__(8) float wsT[25][GG];
    __shared__ __align__(8) float bsh[GG];

    const int tid = threadIdx.x;
    const int v0  = vb * 32;

    for (int idx = tid; idx < 32 * DD; idx += 256) {
        int v = idx / DD, k = idx - v * DD;
        int vg = v0 + v;
        xs[v][k] = (vg < VV) ? emb[(long)vg * DD + k] : 0.f;
    }
    bsh[tid] = bi[tid] + bh[tid];
    __syncthreads();

    const int gg = tid & 31;
    const int vq = tid >> 5;

    u64 acc[4][4];
    #pragma unroll
    for (int j = 0; j < 4; ++j) {
        u64 bp = *(const u64*)&bsh[2 * (gg + 32 * j)];
        #pragma unroll
        for (int v = 0; v < 4; ++v) acc[v][j] = bp;
    }

    for (int kc = 0; kc < 2; ++kc) {
        __syncthreads();
        {
            const float* wp = Wih + (long)tid * DD + kc * 25;
            #pragma unroll
            for (int k = 0; k < 25; ++k) wsT[k][tid] = wp[k];
        }
        __syncthreads();
        #pragma unroll
        for (int k = 0; k < 25; ++k) {
            u64 wv[4];
            #pragma unroll
            for (int j = 0; j < 4; ++j)
                wv[j] = *(const u64*)&wsT[k][2 * (gg + 32 * j)];
            #pragma unroll
            for (int v = 0; v < 4; ++v) {
                float xv = xs[vq * 4 + v][kc * 25 + k];
                u64 xp = pk2(xv, xv);
                #pragma unroll
                for (int j = 0; j < 4; ++j) acc[v][j] = ffma2(wv[j], xp, acc[v][j]);
            }
        }
    }

    #pragma unroll
    for (int v = 0; v < 4; ++v) {
        int vg = v0 + vq * 4 + v;
        if (vg < VV) {
            #pragma unroll
            for (int j = 0; j < 4; ++j)
                *(u64*)(tab + (long)vg * GG + 2 * (gg + 32 * j)) = acc[v][j];
        }
    }
}

// ---------------- recurrent kernel ----------------
__global__ void __launch_bounds__(NTHR, 2) cond_enc_kernel(
    const int*   __restrict__ s1,   const int*   __restrict__ s2,
    const int*   __restrict__ len1, const int*   __restrict__ len2,
    const float* __restrict__ Whh1,
    const float* __restrict__ Whh2,
    const float* __restrict__ Wl1,  const float* __restrict__ bl1,
    const float* __restrict__ Wl2,  const float* __restrict__ bl2,
    float* __restrict__ out)
{
    __shared__ int   toksh[BT][TT];                      // 4 KB
    __shared__ __align__(16) float hA[BT][HP];
    __shared__ __align__(16) float hB[BT][HP];
    __shared__ float pre2[2][BT][GG];                    // partial preacts, 8 KB
    __shared__ float ghh[BT][HH];
    __shared__ float l1sh[BT][128];

    const int tid  = threadIdx.x;
    const int b0   = blockIdx.x * BT;
    const int g    = tid & 255;          // gate row (0..255)
    const int kh   = tid >> 8;           // k-half: 0 -> h[0:32), 1 -> h[32:64)
    const bool k0  = (kh == 0);          // warp-uniform
    const int cr   = tid >> 6;           // combine row (valid when tid<256)
    const int chh  = tid & 63;
    const bool comb = (tid < 256);

    u64   wreg[16];                      // half Whh row (32 floats) as pairs
    float gx[BT], pf[BT];
    float cmy = 0.f;                     // combine-thread state
    float mgh = 0.f, mgc = 0.f;
    int   glmy = -1;

    for (int phase = 0; phase < 2; ++phase) {
        const int*   sent = phase ? s2   : s1;
        const int*   slen = phase ? len2 : len1;
        const float* Whh  = phase ? Whh2 : Whh1;
        const float* tab  = phase ? g_tab1 : g_tab0;

        // ---- this thread's half of the Whh gate row ----
        {
            const float4* hp = (const float4*)(Whh + (long)g * HH + kh * 32);
            #pragma unroll
            for (int q = 0; q < 8; ++q) {
                float4 wv = hp[q];
                wreg[2 * q]     = pk2(wv.x, wv.y);
                wreg[2 * q + 1] = pk2(wv.z, wv.w);
            }
        }
        // ---- stage tokens; init combine state; init hA ----
        for (int idx = tid; idx < BT * TT; idx += NTHR) {
            int r = idx >> 8, t = idx & 255;
            toksh[r][t] = sent[(b0 + r) * TT + t];
        }
        if (comb) {
            glmy = slen[(b0 + cr) * HH + chh];
            cmy  = (phase == 0) ? 0.f : mgc;
            hA[cr][chh] = (phase == 0) ? 0.f : mgh;
        }
        __syncthreads();

        // gate-x for t=0 (only kh=0 threads carry it)
        if (k0) {
            #pragma unroll
            for (int r = 0; r < BT; ++r)
                gx[r] = __ldg(&tab[(long)toksh[r][0] * GG + g]);
        }

        // one LSTM step: read HRD, write HWR, current time TCUR, prefetch TNX
        #define LSTEP(HRD, HWR, TCUR, TNX)                                     \
        {                                                                      \
            if (k0) {                                                          \
                _Pragma("unroll")                                              \
                for (int r = 0; r < BT; ++r)                                   \
                    pf[r] = __ldg(&tab[(long)toksh[r][(TNX)] * GG + g]);       \
            }                                                                  \
            u64 a[BT];                                                         \
            _Pragma("unroll")                                                  \
            for (int r = 0; r < BT; ++r)                                       \
                a[r] = k0 ? pk2(gx[r], 0.f) : 0ULL;                            \
            _Pragma("unroll")                                                  \
            for (int k = 0; k < 8; ++k) {                                      \
                _Pragma("unroll")                                              \
                for (int r = 0; r < BT; ++r) {                                 \
                    ulonglong2 hv = *(const ulonglong2*)&HRD[r][kh * 32 + 4 * k]; \
                    a[r] = ffma2(wreg[2 * k],     hv.x, a[r]);                 \
                    a[r] = ffma2(wreg[2 * k + 1], hv.y, a[r]);                 \
                }                                                              \
            }                                                                  \
            _Pragma("unroll")                                                  \
            for (int r = 0; r < BT; ++r) {                                     \
                pre2[kh][r][g] = pairsum(a[r]);                                \
                if (k0) gx[r] = pf[r];                                         \
            }                                                                  \
            __syncthreads();                                                   \
            if (comb) {                                                        \
                float iv = pre2[0][cr][chh]       + pre2[1][cr][chh];          \
                float fv = pre2[0][cr][64 + chh]  + pre2[1][cr][64 + chh];     \
                float gv = pre2[0][cr][128 + chh] + pre2[1][cr][128 + chh];    \
                float ov = pre2[0][cr][192 + chh] + pre2[1][cr][192 + chh];    \
                float cn = siga(fv) * cmy + siga(iv) * tanha(gv);              \
                float hn = siga(ov) * tanha(cn);                               \
                cmy = cn;                                                      \
                if (glmy == (TCUR)) { mgh = hn; mgc = cn; }                    \
                HWR[cr][chh] = hn;                                             \
            }                                                                  \
            __syncthreads();                                                   \
        }

        #pragma unroll 1
        for (int t = 0; t < TT; t += 2) {
            LSTEP(hA, hB, t,     t + 1)
            LSTEP(hB, hA, t + 1, (t + 2 < TT) ? t + 2 : TT - 1)
        }
        #undef LSTEP
    }

    // publish gathered h for the head
    if (comb) ghh[cr][chh] = mgh;
    __syncthreads();

    // ================= MLP head =================
    {
        int r = tid >> 7, j = tid & 127;                 // 512 = 4 rows x 128
        float acc = bl1[j];
        const float* wr = Wl1 + j * HH;
        #pragma unroll
        for (int k = 0; k < HH; ++k) acc = fmaf(ghh[r][k], wr[k], acc);
        l1sh[r][j] = tanha(acc);
    }
    __syncthreads();
    if (tid < BT * 4) {
        int r = tid >> 2, kk = tid & 3;
        float acc = bl2[kk];
        const float* wr = Wl2 + kk * 128;
        #pragma unroll
        for (int k = 0; k < 128; ++k) acc = fmaf(l1sh[r][k], wr[k], acc);
        out[(b0 + r) * 4 + kk] = acc;
    }
}

extern "C" void kernel_launch(void* const* d_in, const int* in_sizes, int n_in,
                              void* d_out, int out_size)
{
    const int*   s1   = (const int*)  d_in[0];
    const int*   s2   = (const int*)  d_in[1];
    const int*   len1 = (const int*)  d_in[2];
    const int*   len2 = (const int*)  d_in[3];
    // d_in[4], d_in[5] (s1_s, s2_s) unused by the reference model
    const float* emb  = (const float*)d_in[6];
    const float* Wih1 = (const float*)d_in[7];
    const float* Whh1 = (const float*)d_in[8];
    const float* bih1 = (const float*)d_in[9];
    const float* bhh1 = (const float*)d_in[10];
    const float* Wih2 = (const float*)d_in[11];
    const float* Whh2 = (const float*)d_in[12];
    const float* bih2 = (const float*)d_in[13];
    const float* bhh2 = (const float*)d_in[14];
    const float* Wl1  = (const float*)d_in[15];
    const float* bl1  = (const float*)d_in[16];
    const float* Wl2  = (const float*)d_in[17];
    const float* bl2  = (const float*)d_in[18];
    float* out = (float*)d_out;

    precompute_kernel<<<2 * VB, 256>>>(emb, Wih1, bih1, bhh1, Wih2, bih2, bhh2);
    cond_enc_kernel<<<NCTA, NTHR>>>(s1, s2, len1, len2,
                                    Whh1, Whh2, Wl1, bl1, Wl2, bl2, out);
}

// round 7
// speedup vs baseline: 1.4020x; 1.4020x over previous
#include <cuda_runtime.h>

// Conditional encoding: 2-layer LSTM (B=1024, T=256, D=50, H=64) + MLP head.
// x@Wih^T+bias precomputed per vocab entry (32.8MB/layer L2 table).
// Recurrence: 256 CTAs x 4 rows, 2 CTAs/SM, 256 thr. Thread = gate QUAD x
// k-quarter: each LDS.128 of h feeds 4 gates (4x fewer LDS than R4), partials
// packed via STS.128, combine sums 4 partials + table gate-x per (row,ch).

#define BB   1024
#define TT   256
#define DD   50
#define HH   64
#define GG   256   // 4*H
#define VV   32004
#define BT   4     // batch rows per recurrent CTA
#define NCTA 256
#define NTHR 256
#define HP   72    // padded h row stride
#define VB   1001  // ceil(32004/32)

typedef unsigned long long u64;

__device__ float g_tab0[(long)VV * GG];   // layer-1 gate-x table (32.8 MB)
__device__ float g_tab1[(long)VV * GG];   // layer-2 gate-x table

__device__ __forceinline__ u64 pk2(float a, float b) {
    u64 r; asm("mov.b64 %0, {%1, %2};" : "=l"(r) : "f"(a), "f"(b)); return r;
}
__device__ __forceinline__ u64 ffma2(u64 a, u64 b, u64 c) {
    u64 d; asm("fma.rn.f32x2 %0, %1, %2, %3;" : "=l"(d) : "l"(a), "l"(b), "l"(c)); return d;
}
__device__ __forceinline__ float pairsum(u64 a) {
    float x, y; asm("mov.b64 {%0, %1}, %2;" : "=f"(x), "=f"(y) : "l"(a)); return x + y;
}
__device__ __forceinline__ float tanha(float x) {
    float y; asm("tanh.approx.f32 %0, %1;" : "=f"(y) : "f"(x)); return y;
}
__device__ __forceinline__ float siga(float x) {
    return fmaf(0.5f, tanha(0.5f * x), 0.5f);
}

// ---------------- precompute GEMM: tab[v][g] = emb[v].Wih[g] + bih[g]+bhh[g] ----
__global__ void __launch_bounds__(256) precompute_kernel(
    const float* __restrict__ emb,
    const float* __restrict__ WihA, const float* __restrict__ biA, const float* __restrict__ bhA,
    const float* __restrict__ WihB, const float* __restrict__ biB, const float* __restrict__ bhB)
{
    const int layer = blockIdx.x >= VB;
    const int vb    = layer ? blockIdx.x - VB : blockIdx.x;
    const float* Wih = layer ? WihB : WihA;
    const float* bi  = layer ? biB  : biA;
    const float* bh  = layer ? bhB  : bhA;
    float* tab = layer ? g_tab1 : g_tab0;

    __shared__ float xs[32][DD];
    __shared__ __align__(8) float wsT[25][GG];
    __shared__ __align__(8) float bsh[GG];

    const int tid = threadIdx.x;
    const int v0  = vb * 32;

    for (int idx = tid; idx < 32 * DD; idx += 256) {
        int v = idx / DD, k = idx - v * DD;
        int vg = v0 + v;
        xs[v][k] = (vg < VV) ? emb[(long)vg * DD + k] : 0.f;
    }
    bsh[tid] = bi[tid] + bh[tid];
    __syncthreads();

    const int gg = tid & 31;
    const int vq = tid >> 5;

    u64 acc[4][4];
    #pragma unroll
    for (int j = 0; j < 4; ++j) {
        u64 bp = *(const u64*)&bsh[2 * (gg + 32 * j)];
        #pragma unroll
        for (int v = 0; v < 4; ++v) acc[v][j] = bp;
    }

    for (int kc = 0; kc < 2; ++kc) {
        __syncthreads();
        {
            const float* wp = Wih + (long)tid * DD + kc * 25;
            #pragma unroll
            for (int k = 0; k < 25; ++k) wsT[k][tid] = wp[k];
        }
        __syncthreads();
        #pragma unroll
        for (int k = 0; k < 25; ++k) {
            u64 wv[4];
            #pragma unroll
            for (int j = 0; j < 4; ++j)
                wv[j] = *(const u64*)&wsT[k][2 * (gg + 32 * j)];
            #pragma unroll
            for (int v = 0; v < 4; ++v) {
                float xv = xs[vq * 4 + v][kc * 25 + k];
                u64 xp = pk2(xv, xv);
                #pragma unroll
                for (int j = 0; j < 4; ++j) acc[v][j] = ffma2(wv[j], xp, acc[v][j]);
            }
        }
    }

    #pragma unroll
    for (int v = 0; v < 4; ++v) {
        int vg = v0 + vq * 4 + v;
        if (vg < VV) {
            #pragma unroll
            for (int j = 0; j < 4; ++j)
                *(u64*)(tab + (long)vg * GG + 2 * (gg + 32 * j)) = acc[v][j];
        }
    }
}

// ---------------- recurrent kernel ----------------
__global__ void __launch_bounds__(NTHR, 2) cond_enc_kernel(
    const int*   __restrict__ s1,   const int*   __restrict__ s2,
    const int*   __restrict__ len1, const int*   __restrict__ len2,
    const float* __restrict__ Whh1,
    const float* __restrict__ Whh2,
    const float* __restrict__ Wl1,  const float* __restrict__ bl1,
    const float* __restrict__ Wl2,  const float* __restrict__ bl2,
    float* __restrict__ out)
{
    __shared__ int   toksh[BT][TT];                      // 4 KB
    __shared__ __align__(16) float hA[BT][HP];
    __shared__ __align__(16) float hB[BT][HP];
    __shared__ __align__(16) float pre4[4][BT][GG];      // partials, 16 KB
    __shared__ float ghh[BT][HH];
    __shared__ float l1sh[BT][128];

    const int tid = threadIdx.x;
    const int b0  = blockIdx.x * BT;
    const int q   = tid & 63;            // gate quad: gates 4q..4q+3
    const int kq  = tid >> 6;            // k quarter: h[16kq .. 16kq+15]
    const int cr  = tid >> 6;            // combine row
    const int ch  = tid & 63;            // combine channel

    u64   wreg[32];                      // [gi*8+j]: gate 4q+gi, k-pair j
    float gx[4], pfv[4];
    float cmy = 0.f, mgh = 0.f, mgc = 0.f;
    int   glmy = -1;

    for (int phase = 0; phase < 2; ++phase) {
        const int*   sent = phase ? s2   : s1;
        const int*   slen = phase ? len2 : len1;
        const float* Whh  = phase ? Whh2 : Whh1;
        const float* tab  = phase ? g_tab1 : g_tab0;

        // ---- weights: 4 gate rows x 16 k-floats each ----
        #pragma unroll
        for (int gi = 0; gi < 4; ++gi) {
            const float4* wp = (const float4*)(Whh + (long)(4 * q + gi) * HH + 16 * kq);
            #pragma unroll
            for (int j = 0; j < 4; ++j) {
                float4 w = wp[j];
                wreg[gi * 8 + 2 * j]     = pk2(w.x, w.y);
                wreg[gi * 8 + 2 * j + 1] = pk2(w.z, w.w);
            }
        }
        // ---- stage tokens; init combine state; init hA ----
        for (int idx = tid; idx < BT * TT; idx += NTHR) {
            int r = idx >> 8, t = idx & 255;
            toksh[r][t] = sent[(b0 + r) * TT + t];
        }
        glmy = slen[(b0 + cr) * HH + ch];
        cmy  = (phase == 0) ? 0.f : mgc;
        hA[cr][ch] = (phase == 0) ? 0.f : mgh;
        __syncthreads();

        // gate-x for t=0 (combine-side)
        #pragma unroll
        for (int gt = 0; gt < 4; ++gt)
            gx[gt] = __ldg(&tab[(long)toksh[cr][0] * GG + gt * HH + ch]);

        #define LSTEP(HRD, HWR, TCUR, TNX)                                     \
        {                                                                      \
            _Pragma("unroll")                                                  \
            for (int gt = 0; gt < 4; ++gt)                                     \
                pfv[gt] = __ldg(&tab[(long)toksh[cr][(TNX)] * GG + gt * HH + ch]); \
            _Pragma("unroll")                                                  \
            for (int r = 0; r < BT; ++r) {                                     \
                const ulonglong2* hp = (const ulonglong2*)&HRD[r][16 * kq];    \
                ulonglong2 h0 = hp[0], h1 = hp[1], h2 = hp[2], h3 = hp[3];     \
                u64 a0 = 0ULL, a1 = 0ULL, a2 = 0ULL, a3 = 0ULL;                \
                a0 = ffma2(wreg[0], h0.x, a0); a1 = ffma2(wreg[8],  h0.x, a1); \
                a2 = ffma2(wreg[16], h0.x, a2); a3 = ffma2(wreg[24], h0.x, a3);\
                a0 = ffma2(wreg[1], h0.y, a0); a1 = ffma2(wreg[9],  h0.y, a1); \
                a2 = ffma2(wreg[17], h0.y, a2); a3 = ffma2(wreg[25], h0.y, a3);\
                a0 = ffma2(wreg[2], h1.x, a0); a1 = ffma2(wreg[10], h1.x, a1); \
                a2 = ffma2(wreg[18], h1.x, a2); a3 = ffma2(wreg[26], h1.x, a3);\
                a0 = ffma2(wreg[3], h1.y, a0); a1 = ffma2(wreg[11], h1.y, a1); \
                a2 = ffma2(wreg[19], h1.y, a2); a3 = ffma2(wreg[27], h1.y, a3);\
                a0 = ffma2(wreg[4], h2.x, a0); a1 = ffma2(wreg[12], h2.x, a1); \
                a2 = ffma2(wreg[20], h2.x, a2); a3 = ffma2(wreg[28], h2.x, a3);\
                a0 = ffma2(wreg[5], h2.y, a0); a1 = ffma2(wreg[13], h2.y, a1); \
                a2 = ffma2(wreg[21], h2.y, a2); a3 = ffma2(wreg[29], h2.y, a3);\
                a0 = ffma2(wreg[6], h3.x, a0); a1 = ffma2(wreg[14], h3.x, a1); \
                a2 = ffma2(wreg[22], h3.x, a2); a3 = ffma2(wreg[30], h3.x, a3);\
                a0 = ffma2(wreg[7], h3.y, a0); a1 = ffma2(wreg[15], h3.y, a1); \
                a2 = ffma2(wreg[23], h3.y, a2); a3 = ffma2(wreg[31], h3.y, a3);\
                float4 s;                                                      \
                s.x = pairsum(a0); s.y = pairsum(a1);                          \
                s.z = pairsum(a2); s.w = pairsum(a3);                          \
                *(float4*)&pre4[kq][r][4 * q] = s;                             \
            }                                                                  \
            __syncthreads();                                                   \
            {                                                                  \
                float iv = ((pre4[0][cr][ch] + pre4[1][cr][ch])                \
                          + (pre4[2][cr][ch] + pre4[3][cr][ch])) + gx[0];      \
                float fv = ((pre4[0][cr][64 + ch] + pre4[1][cr][64 + ch])      \
                          + (pre4[2][cr][64 + ch] + pre4[3][cr][64 + ch])) + gx[1]; \
                float gv = ((pre4[0][cr][128 + ch] + pre4[1][cr][128 + ch])    \
                          + (pre4[2][cr][128 + ch] + pre4[3][cr][128 + ch])) + gx[2]; \
                float ov = ((pre4[0][cr][192 + ch] + pre4[1][cr][192 + ch])    \
                          + (pre4[2][cr][192 + ch] + pre4[3][cr][192 + ch])) + gx[3]; \
                gx[0] = pfv[0]; gx[1] = pfv[1]; gx[2] = pfv[2]; gx[3] = pfv[3];\
                float cn = siga(fv) * cmy + siga(iv) * tanha(gv);              \
                float hn = siga(ov) * tanha(cn);                               \
                cmy = cn;                                                      \
                if (glmy == (TCUR)) { mgh = hn; mgc = cn; }                    \
                HWR[cr][ch] = hn;                                              \
            }                                                                  \
            __syncthreads();                                                   \
        }

        #pragma unroll 1
        for (int t = 0; t < TT; t += 2) {
            LSTEP(hA, hB, t,     t + 1)
            LSTEP(hB, hA, t + 1, (t + 2 < TT) ? t + 2 : TT - 1)
        }
        #undef LSTEP
    }

    // publish gathered h for the head
    ghh[cr][ch] = mgh;
    __syncthreads();

    // ================= MLP head =================
    #pragma unroll
    for (int qq = 0; qq < 2; ++qq) {
        int p = tid + NTHR * qq;                     // 512 = 4 rows x 128
        int r = p >> 7, j = p & 127;
        float acc = bl1[j];
        const float* wr = Wl1 + j * HH;
        #pragma unroll
        for (int k = 0; k < HH; ++k) acc = fmaf(ghh[r][k], wr[k], acc);
        l1sh[r][j] = tanha(acc);
    }
    __syncthreads();
    if (tid < BT * 4) {
        int r = tid >> 2, kk = tid & 3;
        float acc = bl2[kk];
        const float* wr = Wl2 + kk * 128;
        #pragma unroll
        for (int k = 0; k < 128; ++k) acc = fmaf(l1sh[r][k], wr[k], acc);
        out[(b0 + r) * 4 + kk] = acc;
    }
}

extern "C" void kernel_launch(void* const* d_in, const int* in_sizes, int n_in,
                              void* d_out, int out_size)
{
    const int*   s1   = (const int*)  d_in[0];
    const int*   s2   = (const int*)  d_in[1];
    const int*   len1 = (const int*)  d_in[2];
    const int*   len2 = (const int*)  d_in[3];
    // d_in[4], d_in[5] (s1_s, s2_s) unused by the reference model
    const float* emb  = (const float*)d_in[6];
    const float* Wih1 = (const float*)d_in[7];
    const float* Whh1 = (const float*)d_in[8];
    const float* bih1 = (const float*)d_in[9];
    const float* bhh1 = (const float*)d_in[10];
    const float* Wih2 = (const float*)d_in[11];
    const float* Whh2 = (const float*)d_in[12];
    const float* bih2 = (const float*)d_in[13];
    const float* bhh2 = (const float*)d_in[14];
    const float* Wl1  = (const float*)d_in[15];
    const float* bl1  = (const float*)d_in[16];
    const float* Wl2  = (const float*)d_in[17];
    const float* bl2  = (const float*)d_in[18];
    float* out = (float*)d_out;

    precompute_kernel<<<2 * VB, 256>>>(emb, Wih1, bih1, bhh1, Wih2, bih2, bhh2);
    cond_enc_kernel<<<NCTA, NTHR>>>(s1, s2, len1, len2,
                                    Whh1, Whh2, Wl1, bl1, Wl2, bl2, out);
}

// round 8
// speedup vs baseline: 1.5420x; 1.0999x over previous
#include <cuda_runtime.h>

// Conditional encoding: 2-layer LSTM (B=1024, T=256, D=50, H=64) + MLP head.
// x@Wih^T+bias precomputed per vocab entry; table layout tab[v][ch][{i,f,g,o}]
// so the recurrent combine fetches all 4 gate-x with ONE LDG.128.
// Recurrence: balanced grid 292 = 148 CTAs x 4 rows + 144 CTAs x 3 rows
// (max 7 rows/SM at 2 CTAs/SM). Thread = gate quad x k-quarter (R7 scheme).

#define BB   1024
#define TT   256
#define DD   50
#define HH   64
#define GG   256   // 4*H
#define VV   32004
#define NTHR 256
#define HP   72    // padded h row stride
#define VB   1001  // ceil(32004/32)

typedef unsigned long long u64;

__device__ float g_tab0[(long)VV * GG];   // layer-1 table, [v][ch][4] = i,f,g,o
__device__ float g_tab1[(long)VV * GG];   // layer-2 table

__device__ __forceinline__ u64 pk2(float a, float b) {
    u64 r; asm("mov.b64 %0, {%1, %2};" : "=l"(r) : "f"(a), "f"(b)); return r;
}
__device__ __forceinline__ u64 ffma2(u64 a, u64 b, u64 c) {
    u64 d; asm("fma.rn.f32x2 %0, %1, %2, %3;" : "=l"(d) : "l"(a), "l"(b), "l"(c)); return d;
}
__device__ __forceinline__ float pairsum(u64 a) {
    float x, y; asm("mov.b64 {%0, %1}, %2;" : "=f"(x), "=f"(y) : "l"(a)); return x + y;
}
__device__ __forceinline__ float tanha(float x) {
    float y; asm("tanh.approx.f32 %0, %1;" : "=f"(y) : "f"(x)); return y;
}
__device__ __forceinline__ float siga(float x) {
    return fmaf(0.5f, tanha(0.5f * x), 0.5f);
}

// staging remap: gate g -> bit7 = type>=2, bits[6:1] = channel, bit0 = type&1.
// A u64 read at 2*ch (or 128+2*ch) yields the (typeEven,typeOdd) pair of ch.
__device__ __forceinline__ int remap(int g) {
    return ((g >> 7) << 7) | ((g & 63) << 1) | ((g >> 6) & 1);
}

// ---------------- precompute: tab[v][ch][4] = {i,f,g,o} preacts ----------------
__global__ void __launch_bounds__(256) precompute_kernel(
    const float* __restrict__ emb,
    const float* __restrict__ WihA, const float* __restrict__ biA, const float* __restrict__ bhA,
    const float* __restrict__ WihB, const float* __restrict__ biB, const float* __restrict__ bhB)
{
    const int layer = blockIdx.x >= VB;
    const int vb    = layer ? blockIdx.x - VB : blockIdx.x;
    const float* Wih = layer ? WihB : WihA;
    const float* bi  = layer ? biB  : biA;
    const float* bh  = layer ? bhB  : bhA;
    float* tab = layer ? g_tab1 : g_tab0;

    __shared__ float xs[32][DD];
    __shared__ __align__(8) float wsT[25][GG];
    __shared__ __align__(8) float bsh[GG];

    const int tid = threadIdx.x;
    const int v0  = vb * 32;
    const int rm  = remap(tid);

    for (int idx = tid; idx < 32 * DD; idx += 256) {
        int v = idx / DD, k = idx - v * DD;
        int vg = v0 + v;
        xs[v][k] = (vg < VV) ? emb[(long)vg * DD + k] : 0.f;
    }
    bsh[rm] = bi[tid] + bh[tid];
    __syncthreads();

    const int gg = tid & 31;     // channel base; this thread: ch = gg and gg+32
    const int vq = tid >> 5;     // v-group: rows vq*4 .. +3
    // pair offsets in remapped arrays: j0=(ch=gg, t01) j1=(gg, t23) j2=(gg+32,t01) j3=(gg+32,t23)
    const int off0 = 2 * gg, off1 = 128 + 2 * gg;
    const int off2 = 2 * (gg + 32), off3 = 128 + 2 * (gg + 32);

    u64 acc[4][4];
    {
        u64 b0 = *(const u64*)&bsh[off0], b1 = *(const u64*)&bsh[off1];
        u64 b2 = *(const u64*)&bsh[off2], b3 = *(const u64*)&bsh[off3];
        #pragma unroll
        for (int v = 0; v < 4; ++v) {
            acc[v][0] = b0; acc[v][1] = b1; acc[v][2] = b2; acc[v][3] = b3;
        }
    }

    for (int kc = 0; kc < 2; ++kc) {
        __syncthreads();
        {
            const float* wp = Wih + (long)tid * DD + kc * 25;
            #pragma unroll
            for (int k = 0; k < 25; ++k) wsT[k][rm] = wp[k];
        }
        __syncthreads();
        #pragma unroll
        for (int k = 0; k < 25; ++k) {
            u64 w0 = *(const u64*)&wsT[k][off0];
            u64 w1 = *(const u64*)&wsT[k][off1];
            u64 w2 = *(const u64*)&wsT[k][off2];
            u64 w3 = *(const u64*)&wsT[k][off3];
            #pragma unroll
            for (int v = 0; v < 4; ++v) {
                float xv = xs[vq * 4 + v][kc * 25 + k];
                u64 xp = pk2(xv, xv);
                acc[v][0] = ffma2(w0, xp, acc[v][0]);
                acc[v][1] = ffma2(w1, xp, acc[v][1]);
                acc[v][2] = ffma2(w2, xp, acc[v][2]);
                acc[v][3] = ffma2(w3, xp, acc[v][3]);
            }
        }
    }

    #pragma unroll
    for (int v = 0; v < 4; ++v) {
        int vg = v0 + vq * 4 + v;
        if (vg < VV) {
            float* base = tab + (long)vg * GG;
            *(u64*)(base + 4 * gg)            = acc[v][0];   // (i,f) of ch=gg
            *(u64*)(base + 4 * gg + 2)        = acc[v][1];   // (g,o) of ch=gg
            *(u64*)(base + 4 * (gg + 32))     = acc[v][2];
            *(u64*)(base + 4 * (gg + 32) + 2) = acc[v][3];
        }
    }
}

// ---------------- recurrent core (templated on rows per CTA) ----------------
template <int BT>
__device__ __forceinline__ void run_lstm(
    int b0, int tid,
    const int*   __restrict__ s1,   const int*   __restrict__ s2,
    const int*   __restrict__ len1, const int*   __restrict__ len2,
    const float* __restrict__ Whh1, const float* __restrict__ Whh2,
    const float* __restrict__ Wl1,  const float* __restrict__ bl1,
    const float* __restrict__ Wl2,  const float* __restrict__ bl2,
    float* __restrict__ out,
    int   (*toksh)[TT],
    float (*hA)[HP], float (*hB)[HP],
    float (*pre4)[4][GG],
    float (*ghh)[HH], float (*l1sh)[128])
{
    const int q  = tid & 63;             // gate quad: gates 4q..4q+3
    const int kq = tid >> 6;             // k quarter: h[16kq .. 16kq+15]
    const int cr = tid >> 6;             // combine row
    const int ch = tid & 63;             // combine channel
    const bool comb = (tid < BT * 64);

    u64    wreg[32];                     // [gi*8+j]: gate 4q+gi, k-pair j
    float4 gx4, pf4;
    float  cmy = 0.f, mgh = 0.f, mgc = 0.f;
    int    glmy = -1;

    for (int phase = 0; phase < 2; ++phase) {
        const int*   sent = phase ? s2   : s1;
        const int*   slen = phase ? len2 : len1;
        const float* Whh  = phase ? Whh2 : Whh1;
        const float* tab  = phase ? g_tab1 : g_tab0;

        #pragma unroll
        for (int gi = 0; gi < 4; ++gi) {
            const float4* wp = (const float4*)(Whh + (long)(4 * q + gi) * HH + 16 * kq);
            #pragma unroll
            for (int j = 0; j < 4; ++j) {
                float4 w = wp[j];
                wreg[gi * 8 + 2 * j]     = pk2(w.x, w.y);
                wreg[gi * 8 + 2 * j + 1] = pk2(w.z, w.w);
            }
        }
        for (int idx = tid; idx < BT * TT; idx += NTHR) {
            int r = idx >> 8, t = idx & 255;
            toksh[r][t] = sent[(b0 + r) * TT + t];
        }
        if (comb) {
            glmy = slen[(b0 + cr) * HH + ch];
            cmy  = (phase == 0) ? 0.f : mgc;
            hA[cr][ch] = (phase == 0) ? 0.f : mgh;
        }
        __syncthreads();

        if (comb)
            gx4 = __ldg((const float4*)&tab[(long)toksh[cr][0] * GG + 4 * ch]);

        #define LSTEP(HRD, HWR, TCUR, TNX)                                     \
        {                                                                      \
            if (comb)                                                          \
                pf4 = __ldg((const float4*)&tab[(long)toksh[cr][(TNX)] * GG + 4 * ch]); \
            _Pragma("unroll")                                                  \
            for (int r = 0; r < BT; ++r) {                                     \
                const ulonglong2* hp = (const ulonglong2*)&HRD[r][16 * kq];    \
                ulonglong2 h0 = hp[0], h1 = hp[1], h2 = hp[2], h3 = hp[3];     \
                u64 a0 = 0ULL, a1 = 0ULL, a2 = 0ULL, a3 = 0ULL;                \
                a0 = ffma2(wreg[0], h0.x, a0); a1 = ffma2(wreg[8],  h0.x, a1); \
                a2 = ffma2(wreg[16], h0.x, a2); a3 = ffma2(wreg[24], h0.x, a3);\
                a0 = ffma2(wreg[1], h0.y, a0); a1 = ffma2(wreg[9],  h0.y, a1); \
                a2 = ffma2(wreg[17], h0.y, a2); a3 = ffma2(wreg[25], h0.y, a3);\
                a0 = ffma2(wreg[2], h1.x, a0); a1 = ffma2(wreg[10], h1.x, a1); \
                a2 = ffma2(wreg[18], h1.x, a2); a3 = ffma2(wreg[26], h1.x, a3);\
                a0 = ffma2(wreg[3], h1.y, a0); a1 = ffma2(wreg[11], h1.y, a1); \
                a2 = ffma2(wreg[19], h1.y, a2); a3 = ffma2(wreg[27], h1.y, a3);\
                a0 = ffma2(wreg[4], h2.x, a0); a1 = ffma2(wreg[12], h2.x, a1); \
                a2 = ffma2(wreg[20], h2.x, a2); a3 = ffma2(wreg[28], h2.x, a3);\
                a0 = ffma2(wreg[5], h2.y, a0); a1 = ffma2(wreg[13], h2.y, a1); \
                a2 = ffma2(wreg[21], h2.y, a2); a3 = ffma2(wreg[29], h2.y, a3);\
                a0 = ffma2(wreg[6], h3.x, a0); a1 = ffma2(wreg[14], h3.x, a1); \
                a2 = ffma2(wreg[22], h3.x, a2); a3 = ffma2(wreg[30], h3.x, a3);\
                a0 = ffma2(wreg[7], h3.y, a0); a1 = ffma2(wreg[15], h3.y, a1); \
                a2 = ffma2(wreg[23], h3.y, a2); a3 = ffma2(wreg[31], h3.y, a3);\
                float4 s;                                                      \
                s.x = pairsum(a0); s.y = pairsum(a1);                          \
                s.z = pairsum(a2); s.w = pairsum(a3);                          \
                *(float4*)&pre4[kq][r][4 * q] = s;                             \
            }                                                                  \
            __syncthreads();                                                   \
            if (comb) {                                                        \
                float iv = ((pre4[0][cr][ch] + pre4[1][cr][ch])                \
                          + (pre4[2][cr][ch] + pre4[3][cr][ch])) + gx4.x;      \
                float fv = ((pre4[0][cr][64 + ch] + pre4[1][cr][64 + ch])      \
                          + (pre4[2][cr][64 + ch] + pre4[3][cr][64 + ch])) + gx4.y; \
                float gv = ((pre4[0][cr][128 + ch] + pre4[1][cr][128 + ch])    \
                          + (pre4[2][cr][128 + ch] + pre4[3][cr][128 + ch])) + gx4.z; \
                float ov = ((pre4[0][cr][192 + ch] + pre4[1][cr][192 + ch])    \
                          + (pre4[2][cr][192 + ch] + pre4[3][cr][192 + ch])) + gx4.w; \
                gx4 = pf4;                                                     \
                float cn = siga(fv) * cmy + siga(iv) * tanha(gv);              \
                float hn = siga(ov) * tanha(cn);                               \
                cmy = cn;                                                      \
                if (glmy == (TCUR)) { mgh = hn; mgc = cn; }                    \
                HWR[cr][ch] = hn;                                              \
            }                                                                  \
            __syncthreads();                                                   \
        }

        #pragma unroll 1
        for (int t = 0; t < TT; t += 2) {
            LSTEP(hA, hB, t,     t + 1)
            LSTEP(hB, hA, t + 1, (t + 2 < TT) ? t + 2 : TT - 1)
        }
        #undef LSTEP
    }

    if (comb) ghh[cr][ch] = mgh;
    __syncthreads();

    // ---- MLP head ----
    for (int p = tid; p < BT * 128; p += NTHR) {
        int r = p >> 7, j = p & 127;
        float acc = bl1[j];
        const float* wr = Wl1 + j * HH;
        #pragma unroll
        for (int k = 0; k < HH; ++k) acc = fmaf(ghh[r][k], wr[k], acc);
        l1sh[r][j] = tanha(acc);
    }
    __syncthreads();
    if (tid < BT * 4) {
        int r = tid >> 2, kk = tid & 3;
        float acc = bl2[kk];
        const float* wr = Wl2 + kk * 128;
        #pragma unroll
        for (int k = 0; k < 128; ++k) acc = fmaf(l1sh[r][k], wr[k], acc);
        out[(b0 + r) * 4 + kk] = acc;
    }
}

// 148 CTAs x 4 rows + 144 CTAs x 3 rows = 1024; max 7 rows/SM at 2 CTAs/SM.
__global__ void __launch_bounds__(NTHR, 2) cond_enc_kernel(
    const int*   __restrict__ s1,   const int*   __restrict__ s2,
    const int*   __restrict__ len1, const int*   __restrict__ len2,
    const float* __restrict__ Whh1, const float* __restrict__ Whh2,
    const float* __restrict__ Wl1,  const float* __restrict__ bl1,
    const float* __restrict__ Wl2,  const float* __restrict__ bl2,
    float* __restrict__ out)
{
    __shared__ int   toksh[4][TT];
    __shared__ __align__(16) float hA[4][HP];
    __shared__ __align__(16) float hB[4][HP];
    __shared__ __align__(16) float pre4[4][4][GG];
    __shared__ float ghh[4][HH];
    __shared__ float l1sh[4][128];

    const int tid = threadIdx.x;
    if (blockIdx.x < 148) {
        run_lstm<4>(blockIdx.x * 4, tid, s1, s2, len1, len2, Whh1, Whh2,
                    Wl1, bl1, Wl2, bl2, out, toksh, hA, hB, pre4, ghh, l1sh);
    } else {
        run_lstm<3>(592 + (blockIdx.x - 148) * 3, tid, s1, s2, len1, len2, Whh1, Whh2,
                    Wl1, bl1, Wl2, bl2, out, toksh, hA, hB, pre4, ghh, l1sh);
    }
}

extern "C" void kernel_launch(void* const* d_in, const int* in_sizes, int n_in,
                              void* d_out, int out_size)
{
    const int*   s1   = (const int*)  d_in[0];
    const int*   s2   = (const int*)  d_in[1];
    const int*   len1 = (const int*)  d_in[2];
    const int*   len2 = (const int*)  d_in[3];
    // d_in[4], d_in[5] (s1_s, s2_s) unused by the reference model
    const float* emb  = (const float*)d_in[6];
    const float* Wih1 = (const float*)d_in[7];
    const float* Whh1 = (const float*)d_in[8];
    const float* bih1 = (const float*)d_in[9];
    const float* bhh1 = (const float*)d_in[10];
    const float* Wih2 = (const float*)d_in[11];
    const float* Whh2 = (const float*)d_in[12];
    const float* bih2 = (const float*)d_in[13];
    const float* bhh2 = (const float*)d_in[14];
    const float* Wl1  = (const float*)d_in[15];
    const float* bl1  = (const float*)d_in[16];
    const float* Wl2  = (const float*)d_in[17];
    const float* bl2  = (const float*)d_in[18];
    float* out = (float*)d_out;

    precompute_kernel<<<2 * VB, 256>>>(emb, Wih1, bih1, bhh1, Wih2, bih2, bhh2);
    cond_enc_kernel<<<292, NTHR>>>(s1, s2, len1, len2,
                                   Whh1, Whh2, Wl1, bl1, Wl2, bl2, out);
}